// round 4
// baseline (speedup 1.0000x reference)
#include <cuda_runtime.h>
#include <cuda_bf16.h>

// ---------------------------------------------------------------------------
// Net_40312563041045: 4-layer max-tempered MLP
//   layer(x; W, b) = 0.8 * (W @ x) + 0.2 * max_i(W[o,i]*x[b,i]) + b
// Linear half on tensor cores (bf16 3-split mma.sync, fp32 accum);
// max half scalar (FMUL on fma pipe + FMNMX on alu pipe) — pipes in parallel.
// ---------------------------------------------------------------------------

#define BMp 68   // fp32 smem row pitch (floats)

__device__ __align__(16) float g_buf0[1024 * 512];
__device__ __align__(16) float g_buf1[1024 * 512];

__device__ __forceinline__ void mma_bf16(float* c, const unsigned* a,
                                         unsigned b0, unsigned b1) {
    asm volatile(
        "mma.sync.aligned.m16n8k16.row.col.f32.bf16.bf16.f32 "
        "{%0,%1,%2,%3}, {%4,%5,%6,%7}, {%8,%9}, {%0,%1,%2,%3};"
        : "+f"(c[0]), "+f"(c[1]), "+f"(c[2]), "+f"(c[3])
        : "r"(a[0]), "r"(a[1]), "r"(a[2]), "r"(a[3]), "r"(b0), "r"(b1));
}

// split one float4 into hi/lo bf16 quads and store ([row][k] layout, 8B aligned)
__device__ __forceinline__ void split_store(__nv_bfloat16* hp, __nv_bfloat16* lp,
                                            float4 v) {
    float a[4] = {v.x, v.y, v.z, v.w};
    __nv_bfloat162 h01, h23, l01, l23;
    __nv_bfloat16 h0 = __float2bfloat16(a[0]);
    __nv_bfloat16 h1 = __float2bfloat16(a[1]);
    __nv_bfloat16 h2 = __float2bfloat16(a[2]);
    __nv_bfloat16 h3 = __float2bfloat16(a[3]);
    h01 = __halves2bfloat162(h0, h1);
    h23 = __halves2bfloat162(h2, h3);
    l01 = __halves2bfloat162(__float2bfloat16(a[0] - __bfloat162float(h0)),
                             __float2bfloat16(a[1] - __bfloat162float(h1)));
    l23 = __halves2bfloat162(__float2bfloat16(a[2] - __bfloat162float(h2)),
                             __float2bfloat16(a[3] - __bfloat162float(h3)));
    ((__nv_bfloat162*)hp)[0] = h01;
    ((__nv_bfloat162*)hp)[1] = h23;
    ((__nv_bfloat162*)lp)[0] = l01;
    ((__nv_bfloat162*)lp)[1] = l23;
}

// 64x64 output tile / block, 256 threads. Scalar path: 4x4 reg tile max.
// Tensor path: 8 warps x 4 m16n8 tiles, bf16 3-split, fp32 accumulate.
__global__ __launch_bounds__(256, 1) void tempered_layer(
    const float* __restrict__ X,     // [M, K]
    const float* __restrict__ Wm,    // [N, K]
    const float* __restrict__ bias,  // [N]
    float* __restrict__ Y,           // [M, N]
    int K, int N)
{
    // fp32 transposed tiles (scalar max) union'd with the epilogue lin buffer
    __shared__ union {
        struct { float xs[2][16 * BMp]; float ws[2][16 * BMp]; } t;  // 17408 B
        float lin[64 * 68];                                          // 17408 B
    } u;
    __shared__ __nv_bfloat16 xh[2][64 * 16], xl[2][64 * 16];  // [m][k] hi/lo
    __shared__ __nv_bfloat16 wh[2][64 * 16], wl[2][64 * 16];  // [n][k] hi/lo

    const int tid  = threadIdx.x;
    const int lane = tid & 31;
    const int wrp  = tid >> 5;
    const int tx   = tid & 15;   // scalar N coord
    const int ty   = tid >> 4;   // scalar M coord

    const int row0 = blockIdx.x * 64;
    const int col0 = blockIdx.y * 64;

    // staging map: each thread loads one float4 along K
    const int lm  = tid >> 2;          // 0..63
    const int lk4 = (tid & 3) << 2;    // 0,4,8,12

    const float* Xp = X  + (size_t)(row0 + lm) * K + lk4;
    const float* Wp = Wm + (size_t)(col0 + lm) * K + lk4;

    float4 xr = *(const float4*)Xp;
    float4 wr = *(const float4*)Wp;

    float mx[4][4];
#pragma unroll
    for (int i = 0; i < 4; ++i)
#pragma unroll
        for (int j = 0; j < 4; ++j) mx[i][j] = -3.402823466e38f;

    // mma accumulators: 4 m16n8 tiles per warp
    float acc[4][4];
#pragma unroll
    for (int j = 0; j < 4; ++j)
#pragma unroll
        for (int q = 0; q < 4; ++q) acc[j][q] = 0.0f;

    // mma coords
    const int g  = lane >> 2;          // 0..7
    const int tg = lane & 3;           // 0..3
    const int mr = (wrp & 3) * 16;     // warp M origin
    const int nc = (wrp >> 2) * 32;    // warp N origin

    const int T = K >> 4;

    // stage tile 0
    {
        float* xd = &u.t.xs[0][lk4 * BMp + lm];
        float* wd = &u.t.ws[0][lk4 * BMp + lm];
        xd[0] = xr.x; xd[BMp] = xr.y; xd[2 * BMp] = xr.z; xd[3 * BMp] = xr.w;
        wd[0] = wr.x; wd[BMp] = wr.y; wd[2 * BMp] = wr.z; wd[3 * BMp] = wr.w;
        split_store(&xh[0][lm * 16 + lk4], &xl[0][lm * 16 + lk4], xr);
        split_store(&wh[0][lm * 16 + lk4], &wl[0][lm * 16 + lk4], wr);
    }
    __syncthreads();

    for (int t = 0; t < T; ++t) {
        if (t + 1 < T) {
            xr = *(const float4*)(Xp + (t + 1) * 16);
            wr = *(const float4*)(Wp + (t + 1) * 16);
        }
        const int c = t & 1;

        // ---- tensor path: one k16 step, 3-split bf16 ----
        {
            const __nv_bfloat16* xhb = xh[c];
            const __nv_bfloat16* xlb = xl[c];
            const __nv_bfloat16* whb = wh[c];
            const __nv_bfloat16* wlb = wl[c];
            unsigned ah[4], al[4];
            ah[0] = *(const unsigned*)(xhb + (mr + g)     * 16 + tg * 2);
            ah[1] = *(const unsigned*)(xhb + (mr + g + 8) * 16 + tg * 2);
            ah[2] = *(const unsigned*)(xhb + (mr + g)     * 16 + tg * 2 + 8);
            ah[3] = *(const unsigned*)(xhb + (mr + g + 8) * 16 + tg * 2 + 8);
            al[0] = *(const unsigned*)(xlb + (mr + g)     * 16 + tg * 2);
            al[1] = *(const unsigned*)(xlb + (mr + g + 8) * 16 + tg * 2);
            al[2] = *(const unsigned*)(xlb + (mr + g)     * 16 + tg * 2 + 8);
            al[3] = *(const unsigned*)(xlb + (mr + g + 8) * 16 + tg * 2 + 8);
#pragma unroll
            for (int j = 0; j < 4; ++j) {
                const int n0 = nc + j * 8;
                unsigned bh0 = *(const unsigned*)(whb + (n0 + g) * 16 + tg * 2);
                unsigned bh1 = *(const unsigned*)(whb + (n0 + g) * 16 + tg * 2 + 8);
                unsigned bl0 = *(const unsigned*)(wlb + (n0 + g) * 16 + tg * 2);
                unsigned bl1 = *(const unsigned*)(wlb + (n0 + g) * 16 + tg * 2 + 8);
                mma_bf16(acc[j], ah, bh0, bh1);   // hi*hi
                mma_bf16(acc[j], ah, bl0, bl1);   // hi*lo
                mma_bf16(acc[j], al, bh0, bh1);   // lo*hi
            }
        }

        // ---- scalar path: max only ----
        {
            const float* xb = u.t.xs[c];
            const float* wb = u.t.ws[c];
#pragma unroll
            for (int k = 0; k < 16; ++k) {
                float4 xv = *(const float4*)(xb + k * BMp + 4 * ty);
                float4 wv = *(const float4*)(wb + k * BMp + 4 * tx);
                float xa[4] = {xv.x, xv.y, xv.z, xv.w};
                float wa[4] = {wv.x, wv.y, wv.z, wv.w};
#pragma unroll
                for (int i = 0; i < 4; ++i)
#pragma unroll
                    for (int j = 0; j < 4; ++j)
                        mx[i][j] = fmaxf(mx[i][j], xa[i] * wa[j]);
            }
        }

        if (t + 1 < T) {
            const int nb = (t + 1) & 1;
            float* xd = &u.t.xs[nb][lk4 * BMp + lm];
            float* wd = &u.t.ws[nb][lk4 * BMp + lm];
            xd[0] = xr.x; xd[BMp] = xr.y; xd[2 * BMp] = xr.z; xd[3 * BMp] = xr.w;
            wd[0] = wr.x; wd[BMp] = wr.y; wd[2 * BMp] = wr.z; wd[3 * BMp] = wr.w;
            split_store(&xh[nb][lm * 16 + lk4], &xl[nb][lm * 16 + lk4], xr);
            split_store(&wh[nb][lm * 16 + lk4], &wl[nb][lm * 16 + lk4], wr);
        }
        __syncthreads();
    }

    // ---- epilogue: dump mma accumulators to lin (aliases fp32 tiles) ----
#pragma unroll
    for (int j = 0; j < 4; ++j) {
        const int col = nc + j * 8 + tg * 2;
        *(float2*)(&u.lin[(mr + g)     * 68 + col]) = make_float2(acc[j][0], acc[j][1]);
        *(float2*)(&u.lin[(mr + g + 8) * 68 + col]) = make_float2(acc[j][2], acc[j][3]);
    }
    __syncthreads();

    // combine: out = 0.8*lin + 0.2*max + bias
    const int cbase = col0 + 4 * tx;
    float4 bv = *(const float4*)(bias + cbase);
#pragma unroll
    for (int i = 0; i < 4; ++i) {
        const int r = 4 * ty + i;
        float4 lv = *(const float4*)(&u.lin[r * 68 + 4 * tx]);
        float4 o;
        o.x = 0.8f * lv.x + 0.2f * mx[i][0] + bv.x;
        o.y = 0.8f * lv.y + 0.2f * mx[i][1] + bv.y;
        o.z = 0.8f * lv.z + 0.2f * mx[i][2] + bv.z;
        o.w = 0.8f * lv.w + 0.2f * mx[i][3] + bv.w;
        *(float4*)(Y + (size_t)(row0 + r) * N + cbase) = o;
    }
}

// Final layer: OUT=1. 128 threads per row (one float4 each for K=512),
// warp shuffle + smem cross-warp reduce. Block = 2 rows.
__global__ __launch_bounds__(256) void out_layer(
    const float* __restrict__ H,   // [B, K]
    const float* __restrict__ w4,  // [K]
    const float* __restrict__ b4,  // [1]
    float* __restrict__ out,       // [B]
    int K)
{
    __shared__ float ss[8], sm[8];
    const int tid   = threadIdx.x;
    const int lane  = tid & 31;
    const int wrp   = tid >> 5;
    const int local = tid & 127;          // 0..127 within row
    const int row   = blockIdx.x * 2 + (tid >> 7);

    float s = 0.0f;
    float m = -3.402823466e38f;
    if (local * 4 < K) {
        float4 hv = ((const float4*)(H + (size_t)row * K))[local];
        float4 wv = ((const float4*)w4)[local];
        float p0 = wv.x * hv.x, p1 = wv.y * hv.y;
        float p2 = wv.z * hv.z, p3 = wv.w * hv.w;
        s = (p0 + p1) + (p2 + p3);
        m = fmaxf(fmaxf(p0, p1), fmaxf(p2, p3));
    }
#pragma unroll
    for (int o = 16; o > 0; o >>= 1) {
        s += __shfl_xor_sync(0xFFFFFFFFu, s, o);
        m = fmaxf(m, __shfl_xor_sync(0xFFFFFFFFu, m, o));
    }
    if (lane == 0) { ss[wrp] = s; sm[wrp] = m; }
    __syncthreads();
    if (tid < 2) {
        float fs = (ss[tid * 4] + ss[tid * 4 + 1]) + (ss[tid * 4 + 2] + ss[tid * 4 + 3]);
        float fm = fmaxf(fmaxf(sm[tid * 4], sm[tid * 4 + 1]),
                         fmaxf(sm[tid * 4 + 2], sm[tid * 4 + 3]));
        out[blockIdx.x * 2 + tid] = 0.8f * fs + 0.2f * fm + b4[0];
    }
}

extern "C" void kernel_launch(void* const* d_in, const int* in_sizes, int n_in,
                              void* d_out, int out_size)
{
    const float* x  = (const float*)d_in[0];
    const float* W1 = (const float*)d_in[1];
    const float* b1 = (const float*)d_in[2];
    const float* W2 = (const float*)d_in[3];
    const float* b2 = (const float*)d_in[4];
    const float* W3 = (const float*)d_in[5];
    const float* b3 = (const float*)d_in[6];
    const float* W4 = (const float*)d_in[7];
    const float* b4 = (const float*)d_in[8];

    const int Wd = in_sizes[2];            // hidden width = 512
    const int IN = in_sizes[1] / Wd;       // 256
    const int B  = in_sizes[0] / IN;       // 1024

    float *h0, *h1;
    cudaGetSymbolAddress((void**)&h0, g_buf0);
    cudaGetSymbolAddress((void**)&h1, g_buf1);

    dim3 grid(B / 64, Wd / 64);
    tempered_layer<<<grid, 256>>>(x,  W1, b1, h0, IN, Wd);
    tempered_layer<<<grid, 256>>>(h0, W2, b2, h1, Wd, Wd);
    tempered_layer<<<grid, 256>>>(h1, W3, b3, h0, Wd, Wd);
    out_layer<<<B / 2, 256>>>(h0, W4, b4, (float*)d_out, Wd);
}